// round 4
// baseline (speedup 1.0000x reference)
#include <cuda_runtime.h>

// SphericalExpansion: per-edge radial×angular outer product scattered into
// out[idx_i, z[idx_j], n, m]  (20000, 4, 8, 16) fp32.
//
// Two edges per warp. Compute role: lane = row ln = l*8+n (0..31); ONE set of
// 16 pre-scaled W registers serves BOTH edges (two Horner evaluations with
// broadcast B0/B1). Radial basis via factorization
//   g_k = exp(-2(d-c_k)^2) = A * B^k * C_k,  A=exp(-2d^2), B=exp(4d/3)
//   acc[ln] = A*fc * Horner_k( W[ln,k]*C_k ; B )
// Scatter role: half h (lane>>4), quad q (lane&15) -> two contiguous float4
// segments (quads q and q+16) committed via red.global.add.v4.f32.
// Edge scalars software-pipelined one iteration ahead.

#define PI_F 3.14159265358979f

__device__ __forceinline__ void red_add_v4(float* p, float a, float b, float c, float d) {
    asm volatile("red.global.add.v4.f32 [%0], {%1,%2,%3,%4};"
                 :: "l"(p), "f"(a), "f"(b), "f"(c), "f"(d) : "memory");
}

__global__ __launch_bounds__(256, 5)
void sph_expand_kernel(
    const float* __restrict__ dist,
    const float* __restrict__ dirs,
    const float* __restrict__ W,      // (4, 8, 16) row-major = (32, 16)
    const int*   __restrict__ zarr,   // (N_ATOMS)
    const int*   __restrict__ idx_i,
    const int*   __restrict__ idx_j,
    float*       __restrict__ out,    // (N_ATOMS, 4, 8, 16)
    int n_edges)
{
    const unsigned FULL = 0xffffffffu;
    const int lane = threadIdx.x & 31;
    const int h    = lane >> 4;        // which edge of the pair this lane loads/scatters
    const int q    = lane & 15;

    const int gw = (blockIdx.x * blockDim.x + threadIdx.x) >> 5;
    const int nw = (gridDim.x * blockDim.x) >> 5;

    // Compute role: this lane owns row ln = lane. Pre-scale by C_k.
    float w[16];
    #pragma unroll
    for (int k = 0; k < 16; ++k) {
        float ck = (float)k * (5.0f / 15.0f);
        float C  = __expf(-2.0f * ck * ck);
        w[k] = W[lane * 16 + k] * C;
    }

    // Scatter role: lane (h,q) writes quads q and q+16 of edge e0+h.
    // quad t: n = t>>2, mq = t&3. Quads q and q+16 share mq; n1 = n0 + 4.
    // l(m) per quad: mq0->{0,1,1,1} mq1->{2,2,2,2} mq2->{2,3,3,3} mq3->{3,3,3,3}
    const int n0 = q >> 2;
    const int mq = q & 3;
    const int lA = (mq == 0) ? 0 : (mq == 3 ? 3 : 2);
    const int lB = (mq == 0) ? 1 : (mq == 1 ? 2 : 3);
    const int rA0 = lA * 8 + n0;       // source rows (lanes) in compute role
    const int rB0 = lB * 8 + n0;
    const int rA1 = rA0 + 4;
    const int rB1 = rB0 + 4;

    int e0 = 2 * gw;
    if (e0 >= n_edges) return;

    // ---- prologue: load this half's edge scalars ----
    int  myE   = e0 + h;
    bool valid = myE < n_edges;
    int  le    = valid ? myE : (n_edges - 1);
    float d  = dist[le];
    float x  = dirs[3 * le + 0];
    float y  = dirs[3 * le + 1];
    float zc = dirs[3 * le + 2];
    int   ii = idx_i[le];
    int   zj = zarr[idx_j[le]];

    while (true) {
        // ---- prefetch next pair's scalars (hides idx_j -> zarr chain) ----
        const int e0n = e0 + 2 * nw;
        float dN = 0.f, xN = 0.f, yN = 0.f, zcN = 0.f;
        int iiN = 0, zjN = 0;
        bool validN = false;
        if (e0n < n_edges) {
            int myEN = e0n + h;
            validN   = myEN < n_edges;
            int leN  = validN ? myEN : (n_edges - 1);
            dN  = dist[leN];
            xN  = dirs[3 * leN + 0];
            yN  = dirs[3 * leN + 1];
            zcN = dirs[3 * leN + 2];
            iiN = idx_i[leN];
            zjN = zarr[idx_j[leN]];
        }

        // ---- per-half scalars: cutoff, A, B ----
        float t  = fminf(fmaxf((d - 4.5f) * 2.0f, 0.0f), 1.0f);
        float fc = 0.5f * (__cosf(t * PI_F) + 1.0f);
        float A  = __expf(-2.0f * d * d);
        float B  = __expf((4.0f / 3.0f) * d);
        float sc = A * fc;

        // Broadcast both edges' B and scale to all lanes.
        const float B0  = __shfl_sync(FULL, B,  0);
        const float B1  = __shfl_sync(FULL, B,  16);
        const float sc0 = __shfl_sync(FULL, sc, 0);
        const float sc1 = __shfl_sync(FULL, sc, 16);

        // ---- two Horners over the SAME 16 W registers ----
        float a0 = w[15], a1 = w[15];
        #pragma unroll
        for (int k = 14; k >= 0; --k) {
            a0 = fmaf(a0, B0, w[k]);
            a1 = fmaf(a1, B1, w[k]);
        }
        a0 *= sc0;    // acc[row=lane] for edge e0
        a1 *= sc1;    // acc[row=lane] for edge e0+1

        // ---- bridge to scatter role: 8 shuffles + 4 selects ----
        float pA0 = __shfl_sync(FULL, a0, rA0), qA0 = __shfl_sync(FULL, a1, rA0);
        float pB0 = __shfl_sync(FULL, a0, rB0), qB0 = __shfl_sync(FULL, a1, rB0);
        float pA1 = __shfl_sync(FULL, a0, rA1), qA1 = __shfl_sync(FULL, a1, rA1);
        float pB1 = __shfl_sync(FULL, a0, rB1), qB1 = __shfl_sync(FULL, a1, rB1);
        const float aA0 = h ? qA0 : pA0;
        const float aB0 = h ? qB0 : pB0;
        const float aA1 = h ? qA1 : pA1;
        const float aB1 = h ? qB1 : pB1;

        // ---- real spherical harmonics (this half's direction) ----
        const float x2 = x * x, y2 = y * y, z2 = zc * zc;
        const float Y0  = 0.28209479177387814f;
        const float Y1  = 0.4886025119029199f * y;
        const float Y2  = 0.4886025119029199f * zc;
        const float Y3  = 0.4886025119029199f * x;
        const float Y4  = 1.0925484305920792f * x * y;
        const float Y5  = 1.0925484305920792f * y * zc;
        const float Y6  = 0.31539156525252005f * (3.0f * z2 - 1.0f);
        const float Y7  = 1.0925484305920792f * x * zc;
        const float Y8  = 0.5462742152960396f * (x2 - y2);
        const float Y9  = 0.5900435899266435f * y * (3.0f * x2 - y2);
        const float Y10 = 2.890611442640554f  * x * y * zc;
        const float Y11 = 0.4570457994644658f * y * (5.0f * z2 - 1.0f);
        const float Y12 = 0.3731763325901154f * zc * (5.0f * z2 - 3.0f);
        const float Y13 = 0.4570457994644658f * x * (5.0f * z2 - 1.0f);
        const float Y14 = 1.445305721320277f  * zc * (x2 - y2);
        const float Y15 = 0.5900435899266435f * x * (x2 - 3.0f * y2);

        float s0, s1, s2, s3;
        if (mq == 0)      { s0 = Y0;  s1 = Y1;  s2 = Y2;  s3 = Y3;  }
        else if (mq == 1) { s0 = Y4;  s1 = Y5;  s2 = Y6;  s3 = Y7;  }
        else if (mq == 2) { s0 = Y8;  s1 = Y9;  s2 = Y10; s3 = Y11; }
        else              { s0 = Y12; s1 = Y13; s2 = Y14; s3 = Y15; }

        // out offset: ((ii*4 + zj)*8 + n)*16 + mq*4 ; quads q and q+16.
        const size_t base = ((size_t)ii * 4 + (size_t)zj) * 128 + (size_t)q * 4;
        if (valid) {
            red_add_v4(out + base,      aA0 * s0, aB0 * s1, aB0 * s2, aB0 * s3);
            red_add_v4(out + base + 64, aA1 * s0, aB1 * s1, aB1 * s2, aB1 * s3);
        }

        if (e0n >= n_edges) break;
        e0 = e0n;
        d = dN; x = xN; y = yN; zc = zcN; ii = iiN; zj = zjN; valid = validN;
    }
}

extern "C" void kernel_launch(void* const* d_in, const int* in_sizes, int n_in,
                              void* d_out, int out_size) {
    const float* dist = (const float*)d_in[0];
    const float* dirs = (const float*)d_in[1];
    const float* W    = (const float*)d_in[2];
    // d_in[3] = centers: analytic linspace(0, RC, 16)
    const int* z      = (const int*)d_in[4];
    const int* idx_i  = (const int*)d_in[5];
    const int* idx_j  = (const int*)d_in[6];
    const int n_edges = in_sizes[0];

    cudaMemsetAsync(d_out, 0, (size_t)out_size * sizeof(float), 0);

    const int block = 256;
    const int grid  = 2368;    // 148 SMs x 16 blocks, grid-stride over edge pairs
    sph_expand_kernel<<<grid, block>>>(dist, dirs, W, z, idx_i, idx_j,
                                       (float*)d_out, n_edges);
}

// round 5
// speedup vs baseline: 1.2866x; 1.2866x over previous
#include <cuda_runtime.h>

// SphericalExpansion: per-edge radial×angular outer product scattered into
// out[idx_i, z[idx_j], n, m]  (20000, 4, 8, 16) fp32.
//
// Two edges per warp (halves). Compute role: lane p=(h, l=pos>>2, nl=pos&3)
// evaluates rows (l,nl) and (l,nl+4) of edge e0+h via ONE packed-f32x2 Horner:
//   g_k = exp(-2(d-c_k)^2) = A * B^k * C_k,  A=exp(-2d^2), B=exp(4d/3)
//   acc[row] = A*fc * Horner_k( W[row,k]*C_k ; B )      (B lane-local!)
// Bridge: row placement (c0: n<4 at lane h*16+l*4+n; c1: n>=4) makes each
// reader's 4 fetches come from a uniform register -> 4 shuffles, 0 selects.
// Scatter: lane (h,q) commits quads q and q+16 via red.global.add.v4.f32.

#define PI_F 3.14159265358979f

typedef unsigned long long u64_t;

__device__ __forceinline__ u64_t pack2(float lo, float hi) {
    u64_t r; asm("mov.b64 %0, {%1, %2};" : "=l"(r) : "f"(lo), "f"(hi)); return r;
}
__device__ __forceinline__ void unpack2(u64_t v, float& lo, float& hi) {
    asm("mov.b64 {%0, %1}, %2;" : "=f"(lo), "=f"(hi) : "l"(v));
}
__device__ __forceinline__ u64_t fma2(u64_t a, u64_t b, u64_t c) {
    u64_t d; asm("fma.rn.f32x2 %0, %1, %2, %3;" : "=l"(d) : "l"(a), "l"(b), "l"(c));
    return d;
}
__device__ __forceinline__ u64_t mul2(u64_t a, u64_t b) {
    u64_t d; asm("mul.rn.f32x2 %0, %1, %2;" : "=l"(d) : "l"(a), "l"(b));
    return d;
}
__device__ __forceinline__ void red_add_v4(float* p, float a, float b, float c, float d) {
    asm volatile("red.global.add.v4.f32 [%0], {%1,%2,%3,%4};"
                 :: "l"(p), "f"(a), "f"(b), "f"(c), "f"(d) : "memory");
}

__global__ __launch_bounds__(256)
void sph_expand_kernel(
    const float* __restrict__ dist,
    const float* __restrict__ dirs,
    const float* __restrict__ W,      // (4, 8, 16) row-major = (32, 16)
    const int*   __restrict__ zarr,   // (N_ATOMS)
    const int*   __restrict__ idx_i,
    const int*   __restrict__ idx_j,
    float*       __restrict__ out,    // (N_ATOMS, 4, 8, 16)
    int n_edges)
{
    const unsigned FULL = 0xffffffffu;
    const int lane = threadIdx.x & 31;
    const int h    = lane >> 4;        // which edge of the pair
    const int pos  = lane & 15;

    const int gw = (blockIdx.x * blockDim.x + threadIdx.x) >> 5;
    const int nw = (gridDim.x * blockDim.x) >> 5;

    // ---- compute role: rows (l, nl) and (l, nl+4), l = pos>>2, nl = pos&3 ----
    const int lrow = pos >> 2;
    const int nl   = pos & 3;
    const int ln0  = lrow * 8 + nl;        // row index (l, nl)
    const int ln1  = ln0 + 4;              // row index (l, nl+4)

    // Packed W rows, pre-scaled by C_k = exp(-2 c_k^2).
    u64_t wp[16];
    #pragma unroll
    for (int k = 0; k < 16; ++k) {
        float ck = (float)k * (5.0f / 15.0f);
        float C  = __expf(-2.0f * ck * ck);
        wp[k] = pack2(W[ln0 * 16 + k] * C, W[ln1 * 16 + k] * C);
    }

    // ---- scatter role: lane (h,q) with q=pos -> quads q and q+16 ----
    // quad q: n0 = q>>2, mq = q&3. l(m) per quad:
    //   mq0->{0,1,1,1} mq1->{2,2,2,2} mq2->{2,3,3,3} mq3->{3,3,3,3}
    const int n0 = pos >> 2;
    const int mq = pos & 3;
    const int lA = (mq == 0) ? 0 : (mq == 3 ? 3 : 2);
    const int lB = (mq == 0) ? 1 : (mq == 1 ? 2 : 3);
    const int srcA = (lane & 16) + lA * 4 + n0;   // source lane for rows (lA, n0 / n0+4)
    const int srcB = (lane & 16) + lB * 4 + n0;

    for (int e0 = 2 * gw; e0 < n_edges; e0 += 2 * nw) {
        const int  myE   = e0 + h;
        const bool valid = myE < n_edges;
        const int  le    = valid ? myE : (n_edges - 1);

        const float d  = dist[le];
        const float x  = dirs[3 * le + 0];
        const float y  = dirs[3 * le + 1];
        const float zc = dirs[3 * le + 2];
        const int   ii = idx_i[le];
        const int   zj = zarr[idx_j[le]];

        // cutoff + radial factorization scalars (all lane-local, edge h)
        float t  = fminf(fmaxf((d - 4.5f) * 2.0f, 0.0f), 1.0f);
        float fc = 0.5f * (__cosf(t * PI_F) + 1.0f);
        float A  = __expf(-2.0f * d * d);
        float B  = __expf((4.0f / 3.0f) * d);
        float sc = A * fc;

        // ---- packed Horner: both rows at once ----
        const u64_t Bp  = pack2(B, B);
        u64_t acc = wp[15];
        #pragma unroll
        for (int k = 14; k >= 0; --k) acc = fma2(acc, Bp, wp[k]);
        acc = mul2(acc, pack2(sc, sc));

        float c0, c1;                 // c0: row (l,nl)   c1: row (l,nl+4)
        unpack2(acc, c0, c1);

        // ---- bridge: 4 shuffles, uniform source registers ----
        const float aA0 = __shfl_sync(FULL, c0, srcA);  // (lA, n0)
        const float aB0 = __shfl_sync(FULL, c0, srcB);  // (lB, n0)
        const float aA1 = __shfl_sync(FULL, c1, srcA);  // (lA, n0+4)
        const float aB1 = __shfl_sync(FULL, c1, srcB);  // (lB, n0+4)

        // ---- real spherical harmonics l<=3 (this half's direction) ----
        const float x2 = x * x, y2 = y * y, z2 = zc * zc;
        const float Y0  = 0.28209479177387814f;
        const float Y1  = 0.4886025119029199f * y;
        const float Y2  = 0.4886025119029199f * zc;
        const float Y3  = 0.4886025119029199f * x;
        const float Y4  = 1.0925484305920792f * x * y;
        const float Y5  = 1.0925484305920792f * y * zc;
        const float Y6  = 0.31539156525252005f * (3.0f * z2 - 1.0f);
        const float Y7  = 1.0925484305920792f * x * zc;
        const float Y8  = 0.5462742152960396f * (x2 - y2);
        const float Y9  = 0.5900435899266435f * y * (3.0f * x2 - y2);
        const float Y10 = 2.890611442640554f  * x * y * zc;
        const float Y11 = 0.4570457994644658f * y * (5.0f * z2 - 1.0f);
        const float Y12 = 0.3731763325901154f * zc * (5.0f * z2 - 3.0f);
        const float Y13 = 0.4570457994644658f * x * (5.0f * z2 - 1.0f);
        const float Y14 = 1.445305721320277f  * zc * (x2 - y2);
        const float Y15 = 0.5900435899266435f * x * (x2 - 3.0f * y2);

        float s0, s1, s2, s3;
        if (mq == 0)      { s0 = Y0;  s1 = Y1;  s2 = Y2;  s3 = Y3;  }
        else if (mq == 1) { s0 = Y4;  s1 = Y5;  s2 = Y6;  s3 = Y7;  }
        else if (mq == 2) { s0 = Y8;  s1 = Y9;  s2 = Y10; s3 = Y11; }
        else              { s0 = Y12; s1 = Y13; s2 = Y14; s3 = Y15; }

        // out offset: ((ii*4 + zj)*8 + n)*16 + mq*4 ; quads q and q+16.
        const size_t base = ((size_t)ii * 4 + (size_t)zj) * 128 + (size_t)pos * 4;
        if (valid) {
            red_add_v4(out + base,      aA0 * s0, aB0 * s1, aB0 * s2, aB0 * s3);
            red_add_v4(out + base + 64, aA1 * s0, aB1 * s1, aB1 * s2, aB1 * s3);
        }
    }
}

extern "C" void kernel_launch(void* const* d_in, const int* in_sizes, int n_in,
                              void* d_out, int out_size) {
    const float* dist = (const float*)d_in[0];
    const float* dirs = (const float*)d_in[1];
    const float* W    = (const float*)d_in[2];
    // d_in[3] = centers: analytic linspace(0, RC, 16)
    const int* z      = (const int*)d_in[4];
    const int* idx_i  = (const int*)d_in[5];
    const int* idx_j  = (const int*)d_in[6];
    const int n_edges = in_sizes[0];

    cudaMemsetAsync(d_out, 0, (size_t)out_size * sizeof(float), 0);

    const int block = 256;
    const int grid  = 2368;    // 148 SMs x 16 blocks, grid-stride over edge pairs
    sph_expand_kernel<<<grid, block>>>(dist, dirs, W, z, idx_i, idx_j,
                                       (float*)d_out, n_edges);
}